// round 1
// baseline (speedup 1.0000x reference)
#include <cuda_runtime.h>

typedef unsigned long long u64;

__device__ __forceinline__ u64 fma2(u64 a, u64 b, u64 c) {
    u64 d;
    asm("fma.rn.f32x2 %0, %1, %2, %3;" : "=l"(d) : "l"(a), "l"(b), "l"(c));
    return d;
}
__device__ __forceinline__ void unpack2(u64 v, float& lo, float& hi) {
    asm("mov.b64 {%0, %1}, %2;" : "=f"(lo), "=f"(hi) : "l"(v));
}

// Smem strides (in floats), chosen for bank behavior:
//  q: 66  -> 4-row-strided broadcast loads hit distinct bank pairs
//  k: 64  + XOR swizzle on 8-byte granules -> conflict-free QK column loads
//  v: 68  -> 16B-aligned rows for LDS.128 (2-way, bandwidth-optimal)
//  p: 132 + XOR swizzle on 16B granules   -> conflict-free PV row loads
#define RQ 66
#define RV 68
#define RP 132
#define OFF_K 4224
#define OFF_V 8320
#define OFF_P 12672
#define SMEM_BYTES (21120 * 4)

__global__ void __launch_bounds__(128, 2)
attn64_f32x2(const float* __restrict__ qg_, const float* __restrict__ kg_,
             const float* __restrict__ vg_, const int* __restrict__ mg_,
             float* __restrict__ og_)
{
    extern __shared__ float sm[];
    float* q_s = sm;
    float* k_s = sm + OFF_K;
    float* v_s = sm + OFF_V;
    float* p_s = sm + OFF_P;

    const int bhn = blockIdx.x;          // 0..8191
    const int b   = bhn >> 9;            // / (H*N) = /512
    const float* qg = qg_ + (size_t)bhn * 4096;
    const float* kg = kg_ + (size_t)bhn * 4096;
    const float* vg = vg_ + (size_t)bhn * 4096;
    const int*   mg = mg_ + (size_t)b   * 4096;
    float*       og = og_ + (size_t)bhn * 4096;

    const int tid = threadIdx.x;
    const int ty  = tid >> 3;            // 0..15 -> rows 4*ty..4*ty+3
    const int tx  = tid & 7;             // 0..7  -> cols 8*tx..8*tx+7

    // ---- Prefetch mask tile into registers (hides L2 latency under QK) ----
    int4 mrow[4][2];
    #pragma unroll
    for (int i = 0; i < 4; i++) {
        const int4* p = reinterpret_cast<const int4*>(mg + (4*ty + i) * 64 + 8*tx);
        mrow[i][0] = p[0];
        mrow[i][1] = p[1];
    }

    // ---- Cooperative coalesced loads: gmem -> smem ----
    #pragma unroll
    for (int it = 0; it < 8; it++) {
        int idx4 = tid + it * 128;
        int e  = idx4 << 2;              // element index 0..4095, step 4
        int r  = e >> 6;                 // row 0..63
        int d0 = e & 63;                 // col 0..60 (mult of 4)
        float4 fq = *reinterpret_cast<const float4*>(qg + e);
        float4 fk = *reinterpret_cast<const float4*>(kg + e);
        float4 fv = *reinterpret_cast<const float4*>(vg + e);
        // q: padded stride, two 8B stores (row start not 16B aligned)
        *reinterpret_cast<float2*>(&q_s[r*RQ + d0    ]) = make_float2(fq.x, fq.y);
        *reinterpret_cast<float2*>(&q_s[r*RQ + d0 + 2]) = make_float2(fq.z, fq.w);
        // k: swizzled on 8B granules: granule g stored at (g ^ (row>>3))
        int g0 = d0 >> 1;                // even
        int s  = r >> 3;
        *reinterpret_cast<float2*>(&k_s[(r<<6) + (((g0    ) ^ s) << 1)]) = make_float2(fk.x, fk.y);
        *reinterpret_cast<float2*>(&k_s[(r<<6) + (((g0 + 1) ^ s) << 1)]) = make_float2(fk.z, fk.w);
        // v: natural, padded stride, 16B aligned
        *reinterpret_cast<float4*>(&v_s[r*RV + d0]) = fv;
    }
    __syncthreads();

    // ---- S = Q K^T  (packed over d: 2 MACs per FFMA2) ----
    u64 acc[4][8];
    #pragma unroll
    for (int i = 0; i < 4; i++)
        #pragma unroll
        for (int j = 0; j < 8; j++) acc[i][j] = 0ull;

    int qrow[4], krow[8];
    #pragma unroll
    for (int i = 0; i < 4; i++) qrow[i] = (4*ty + i) * RQ;
    #pragma unroll
    for (int j = 0; j < 8; j++) krow[j] = (8*tx + j) << 6;

    #pragma unroll 4
    for (int g = 0; g < 32; g++) {       // granule = 2 d's
        int koff = ((g ^ tx) << 1);      // conflict-free swizzled column offset
        u64 qv[4], kv[8];
        #pragma unroll
        for (int i = 0; i < 4; i++)
            qv[i] = *reinterpret_cast<const u64*>(&q_s[qrow[i] + (g << 1)]);
        #pragma unroll
        for (int j = 0; j < 8; j++)
            kv[j] = *reinterpret_cast<const u64*>(&k_s[krow[j] + koff]);
        #pragma unroll
        for (int i = 0; i < 4; i++)
            #pragma unroll
            for (int j = 0; j < 8; j++)
                acc[i][j] = fma2(qv[i], kv[j], acc[i][j]);
    }

    // ---- Softmax over k (rows split across the 8 tx lanes) ----
    #pragma unroll
    for (int i = 0; i < 4; i++) {
        int mm[8];
        mm[0] = mrow[i][0].x; mm[1] = mrow[i][0].y; mm[2] = mrow[i][0].z; mm[3] = mrow[i][0].w;
        mm[4] = mrow[i][1].x; mm[5] = mrow[i][1].y; mm[6] = mrow[i][1].z; mm[7] = mrow[i][1].w;
        float sv[8];
        #pragma unroll
        for (int j = 0; j < 8; j++) {
            float lo, hi;
            unpack2(acc[i][j], lo, hi);
            float t = (lo + hi) * 0.125f;        // / TEMPERATURE
            sv[j] = (mm[j] == 0) ? -32768.0f : t; // MASK_FILL
        }
        float mx = sv[0];
        #pragma unroll
        for (int j = 1; j < 8; j++) mx = fmaxf(mx, sv[j]);
        mx = fmaxf(mx, __shfl_xor_sync(0xffffffffu, mx, 1));
        mx = fmaxf(mx, __shfl_xor_sync(0xffffffffu, mx, 2));
        mx = fmaxf(mx, __shfl_xor_sync(0xffffffffu, mx, 4));
        float pv[8], sum = 0.0f;
        #pragma unroll
        for (int j = 0; j < 8; j++) { pv[j] = __expf(sv[j] - mx); sum += pv[j]; }
        sum += __shfl_xor_sync(0xffffffffu, sum, 1);
        sum += __shfl_xor_sync(0xffffffffu, sum, 2);
        sum += __shfl_xor_sync(0xffffffffu, sum, 4);
        float inv = 1.0f / sum;
        // Store P pre-duplicated as (p,p) pairs, swizzled on 16B granules:
        // granule h = c>>1 stored at (h ^ ((row>>3)&1))
        int r  = 4*ty + i;
        int hb = (r >> 3) & 1;
        int base = r * RP;
        #pragma unroll
        for (int j = 0; j < 8; j++) {
            float p = pv[j] * inv;
            int c = 8*tx + j;
            int w = base + (((c >> 1) ^ hb) << 2) + ((c & 1) << 1);
            *reinterpret_cast<float2*>(&p_s[w]) = make_float2(p, p);
        }
    }
    __syncthreads();

    // ---- O = P V  (packed over output dim dd) ----
    u64 oacc[4][4];
    #pragma unroll
    for (int i = 0; i < 4; i++)
        #pragma unroll
        for (int j = 0; j < 4; j++) oacc[i][j] = 0ull;

    int prow[4], phb[4];
    #pragma unroll
    for (int i = 0; i < 4; i++) {
        int r = 4*ty + i;
        prow[i] = r * RP;
        phb[i]  = (r >> 3) & 1;
    }
    const int vcol = tx << 3;

    #pragma unroll 4
    for (int k2 = 0; k2 < 64; k2 += 2) {
        ulonglong2 pp[4];
        #pragma unroll
        for (int i = 0; i < 4; i++)
            pp[i] = *reinterpret_cast<const ulonglong2*>(
                        &p_s[prow[i] + (((k2 >> 1) ^ phb[i]) << 2)]);
        ulonglong2 va = *reinterpret_cast<const ulonglong2*>(&v_s[ k2      * RV + vcol    ]);
        ulonglong2 vb = *reinterpret_cast<const ulonglong2*>(&v_s[ k2      * RV + vcol + 4]);
        ulonglong2 vc = *reinterpret_cast<const ulonglong2*>(&v_s[(k2 + 1) * RV + vcol    ]);
        ulonglong2 vd = *reinterpret_cast<const ulonglong2*>(&v_s[(k2 + 1) * RV + vcol + 4]);
        #pragma unroll
        for (int i = 0; i < 4; i++) {
            oacc[i][0] = fma2(pp[i].x, va.x, oacc[i][0]);
            oacc[i][1] = fma2(pp[i].x, va.y, oacc[i][1]);
            oacc[i][2] = fma2(pp[i].x, vb.x, oacc[i][2]);
            oacc[i][3] = fma2(pp[i].x, vb.y, oacc[i][3]);
            oacc[i][0] = fma2(pp[i].y, vc.x, oacc[i][0]);
            oacc[i][1] = fma2(pp[i].y, vc.y, oacc[i][1]);
            oacc[i][2] = fma2(pp[i].y, vd.x, oacc[i][2]);
            oacc[i][3] = fma2(pp[i].y, vd.y, oacc[i][3]);
        }
    }

    // ---- Stage outputs through smem (reuse q_s) for fully coalesced stores ----
    #pragma unroll
    for (int i = 0; i < 4; i++) {
        int base = (4*ty + i) * RQ + (tx << 3);
        *reinterpret_cast<u64*>(&q_s[base    ]) = oacc[i][0];
        *reinterpret_cast<u64*>(&q_s[base + 2]) = oacc[i][1];
        *reinterpret_cast<u64*>(&q_s[base + 4]) = oacc[i][2];
        *reinterpret_cast<u64*>(&q_s[base + 6]) = oacc[i][3];
    }
    __syncthreads();
    #pragma unroll
    for (int it = 0; it < 8; it++) {
        int idx4 = tid + it * 128;
        int e  = idx4 << 2;
        int r  = e >> 6;
        int d0 = e & 63;
        float2 a  = *reinterpret_cast<const float2*>(&q_s[r*RQ + d0    ]);
        float2 bb = *reinterpret_cast<const float2*>(&q_s[r*RQ + d0 + 2]);
        *reinterpret_cast<float4*>(og + e) = make_float4(a.x, a.y, bb.x, bb.y);
    }
}

extern "C" void kernel_launch(void* const* d_in, const int* in_sizes, int n_in,
                              void* d_out, int out_size) {
    const float* q    = (const float*)d_in[0];
    const float* k    = (const float*)d_in[1];
    const float* v    = (const float*)d_in[2];
    const int*   mask = (const int*)  d_in[3];
    float*       out  = (float*)d_out;

    cudaFuncSetAttribute(attn64_f32x2,
                         cudaFuncAttributeMaxDynamicSharedMemorySize, SMEM_BYTES);
    attn64_f32x2<<<8192, 128, SMEM_BYTES>>>(q, k, v, mask, out);
}

// round 2
// speedup vs baseline: 1.3951x; 1.3951x over previous
#include <cuda_runtime.h>

typedef unsigned long long u64;

__device__ __forceinline__ u64 fma2(u64 a, u64 b, u64 c) {
    u64 d;
    asm("fma.rn.f32x2 %0, %1, %2, %3;" : "=l"(d) : "l"(a), "l"(b), "l"(c));
    return d;
}
__device__ __forceinline__ void unpack2(u64 v, float& lo, float& hi) {
    asm("mov.b64 {%0, %1}, %2;" : "=f"(lo), "=f"(hi) : "l"(v));
}

// Smem plan (floats), 16384 total = 64KB -> 3 CTAs/SM:
//  [0,8192)     Q (stride 64, granule-ROTATED)  ... later P (stride 128, rotated, (p,p) dup)
//  [8192,12288) K (stride 64, granule-XOR-swizzled) ... later O staging (natural)
//  [12288,16384) V (stride 64, natural; conflict-freedom via per-lane granule permutation)
#define OFF_KS 8192
#define OFF_VS 12288
#define SMEM_BYTES (16384 * 4)

__global__ void __launch_bounds__(128, 3)
attn64_v2(const float* __restrict__ qg_, const float* __restrict__ kg_,
          const float* __restrict__ vg_, const int* __restrict__ mg_,
          float* __restrict__ og_)
{
    extern __shared__ float sm[];
    float* qp_s = sm;            // Q then P
    float* k_s  = sm + OFF_KS;   // K then O staging
    float* v_s  = sm + OFF_VS;   // V

    const int bhn = blockIdx.x;              // 0..8191
    const int b   = bhn >> 9;                // / (H*N)
    const float* qg = qg_ + (size_t)bhn * 4096;
    const float* kg = kg_ + (size_t)bhn * 4096;
    const float* vg = vg_ + (size_t)bhn * 4096;
    const int*   mg = mg_ + (size_t)b   * 4096;
    float*       og = og_ + (size_t)bhn * 4096;

    const int tid = threadIdx.x;
    const int ty  = tid >> 3;                // 0..15 -> rows 4*ty..4*ty+3
    const int tx  = tid & 7;                 // 0..7  -> cols 8*tx..8*tx+7
    const int qr  = ty << 1;                 // rotation amount for this thread's rows

    // ---- Input staging: fully coalesced 16B gmem loads -> swizzled smem ----
    #pragma unroll
    for (int it = 0; it < 8; it++) {
        int e  = (tid + (it << 7)) << 2;     // element index, step 4
        int r  = e >> 6;
        int d0 = e & 63;
        int h  = d0 >> 2;                    // 16B granule index 0..15
        float4 fq = *reinterpret_cast<const float4*>(qg + e);
        float4 fk = *reinterpret_cast<const float4*>(kg + e);
        float4 fv = *reinterpret_cast<const float4*>(vg + e);
        *reinterpret_cast<float4*>(&qp_s[(r << 6) + (((h + ((r >> 2) << 1)) & 15) << 2)]) = fq;
        *reinterpret_cast<float4*>(&k_s [(r << 6) + ((h ^ (r >> 3)) << 2)])               = fk;
        *reinterpret_cast<float4*>(&v_s [(r << 6) + d0])                                   = fv;
    }
    __syncthreads();

    // ---- S = Q K^T : packed over d, all LDS.128 conflict-free ----
    u64 acc[4][8];
    #pragma unroll
    for (int i = 0; i < 4; i++)
        #pragma unroll
        for (int j = 0; j < 8; j++) acc[i][j] = 0ull;

    const float* qrow0 = qp_s + ((ty << 2) << 6);   // row 4ty
    const float* krow0 = k_s  + ((tx << 3) << 6);   // row 8tx

    #pragma unroll 4
    for (int g = 0; g < 16; g++) {
        const float* qptr = qrow0 + (((g + qr) & 15) << 2);  // rotation: rows spread over bank groups
        const float* kptr = krow0 + ((g ^ tx) << 2);          // XOR: full 128B wavefront
        ulonglong2 qv[4], kv[8];
        #pragma unroll
        for (int i = 0; i < 4; i++)
            qv[i] = *reinterpret_cast<const ulonglong2*>(qptr + (i << 6));
        #pragma unroll
        for (int j = 0; j < 8; j++)
            kv[j] = *reinterpret_cast<const ulonglong2*>(kptr + (j << 6));
        #pragma unroll
        for (int i = 0; i < 4; i++)
            #pragma unroll
            for (int j = 0; j < 8; j++) {
                acc[i][j] = fma2(qv[i].x, kv[j].x, acc[i][j]);
                acc[i][j] = fma2(qv[i].y, kv[j].y, acc[i][j]);
            }
    }
    __syncthreads();   // Q region dead everywhere -> safe to overwrite with P

    // ---- Mask fetch (L2-resident; 512 CTAs/slice) + softmax in registers ----
    int4 ma[4], mb[4];
    {
        const int* mrow = mg + (tx << 3);
        #pragma unroll
        for (int i = 0; i < 4; i++) {
            ma[i] = *reinterpret_cast<const int4*>(mrow + (((ty << 2) + i) << 6));
            mb[i] = *reinterpret_cast<const int4*>(mrow + (((ty << 2) + i) << 6) + 4);
        }
    }

    float* prow0 = qp_s + ((ty << 2) << 7);   // P: row 4ty, stride 128
    #pragma unroll
    for (int i = 0; i < 4; i++) {
        int mm[8] = {ma[i].x, ma[i].y, ma[i].z, ma[i].w,
                     mb[i].x, mb[i].y, mb[i].z, mb[i].w};
        float sv[8];
        #pragma unroll
        for (int j = 0; j < 8; j++) {
            float lo, hi;
            unpack2(acc[i][j], lo, hi);
            float t = (lo + hi) * 0.125f;          // / TEMPERATURE
            sv[j] = (mm[j] == 0) ? -32768.0f : t;  // MASK_FILL
        }
        float mx = sv[0];
        #pragma unroll
        for (int j = 1; j < 8; j++) mx = fmaxf(mx, sv[j]);
        mx = fmaxf(mx, __shfl_xor_sync(0xffffffffu, mx, 1));
        mx = fmaxf(mx, __shfl_xor_sync(0xffffffffu, mx, 2));
        mx = fmaxf(mx, __shfl_xor_sync(0xffffffffu, mx, 4));
        float pv[8], sum = 0.0f;
        #pragma unroll
        for (int j = 0; j < 8; j++) { pv[j] = __expf(sv[j] - mx); sum += pv[j]; }
        sum += __shfl_xor_sync(0xffffffffu, sum, 1);
        sum += __shfl_xor_sync(0xffffffffu, sum, 2);
        sum += __shfl_xor_sync(0xffffffffu, sum, 4);
        float inv = 1.0f / sum;
        // Store P pre-duplicated (p0,p0,p1,p1) per 16B granule, rotated:
        // granule h = 4tx+jg holds cols (2h, 2h+1); position (h + 2*ty) & 31.
        float* pr = prow0 + (i << 7);
        #pragma unroll
        for (int jg = 0; jg < 4; jg++) {
            int hgr = (((tx << 2) + jg + qr) & 31) << 2;
            float p0 = pv[2 * jg]     * inv;
            float p1 = pv[2 * jg + 1] * inv;
            *reinterpret_cast<float4*>(pr + hgr) = make_float4(p0, p0, p1, p1);
        }
    }
    __syncthreads();

    // ---- O = P V : packed over d; V lanes permuted over bank groups ----
    u64 oA[4][2], oB[4][2];
    #pragma unroll
    for (int i = 0; i < 4; i++) {
        oA[i][0] = oA[i][1] = 0ull;
        oB[i][0] = oB[i][1] = 0ull;
    }
    const int perm = (tx >> 2) & 1;
    const int offA = (((tx << 1) + perm)     << 2);   // granule gA -> ds 4gA..4gA+3
    const int offB = (((tx << 1) + 1 - perm) << 2);   // granule gB

    #pragma unroll 4
    for (int k2 = 0; k2 < 64; k2 += 2) {
        const float* pptr = prow0 + ((((k2 >> 1) + qr) & 31) << 2);
        ulonglong2 pp[4];
        #pragma unroll
        for (int i = 0; i < 4; i++)
            pp[i] = *reinterpret_cast<const ulonglong2*>(pptr + (i << 7));
        const float* vk = v_s + (k2 << 6);
        ulonglong2 vA0 = *reinterpret_cast<const ulonglong2*>(vk + offA);
        ulonglong2 vB0 = *reinterpret_cast<const ulonglong2*>(vk + offB);
        ulonglong2 vA1 = *reinterpret_cast<const ulonglong2*>(vk + 64 + offA);
        ulonglong2 vB1 = *reinterpret_cast<const ulonglong2*>(vk + 64 + offB);
        #pragma unroll
        for (int i = 0; i < 4; i++) {
            oA[i][0] = fma2(pp[i].x, vA0.x, oA[i][0]);
            oA[i][1] = fma2(pp[i].x, vA0.y, oA[i][1]);
            oB[i][0] = fma2(pp[i].x, vB0.x, oB[i][0]);
            oB[i][1] = fma2(pp[i].x, vB0.y, oB[i][1]);
            oA[i][0] = fma2(pp[i].y, vA1.x, oA[i][0]);
            oA[i][1] = fma2(pp[i].y, vA1.y, oA[i][1]);
            oB[i][0] = fma2(pp[i].y, vB1.x, oB[i][0]);
            oB[i][1] = fma2(pp[i].y, vB1.y, oB[i][1]);
        }
    }

    // ---- Stage O into k_s (natural layout; perm undone by address) ----
    // Safe without a barrier: every warp passed the post-P-store barrier,
    // so no warp can still be reading k_s (QK) here.
    #pragma unroll
    for (int i = 0; i < 4; i++) {
        float* orow = k_s + (((ty << 2) + i) << 6);
        ulonglong2 tA; tA.x = oA[i][0]; tA.y = oA[i][1];
        ulonglong2 tB; tB.x = oB[i][0]; tB.y = oB[i][1];
        *reinterpret_cast<ulonglong2*>(orow + offA) = tA;
        *reinterpret_cast<ulonglong2*>(orow + offB) = tB;
    }
    __syncthreads();

    // ---- Fully coalesced 16B stores ----
    #pragma unroll
    for (int it = 0; it < 8; it++) {
        int e = (tid + (it << 7)) << 2;
        *reinterpret_cast<float4*>(og + e) =
            *reinterpret_cast<const float4*>(k_s + e);
    }
}

extern "C" void kernel_launch(void* const* d_in, const int* in_sizes, int n_in,
                              void* d_out, int out_size) {
    const float* q    = (const float*)d_in[0];
    const float* k    = (const float*)d_in[1];
    const float* v    = (const float*)d_in[2];
    const int*   mask = (const int*)  d_in[3];
    float*       out  = (float*)d_out;

    cudaFuncSetAttribute(attn64_v2,
                         cudaFuncAttributeMaxDynamicSharedMemorySize, SMEM_BYTES);
    attn64_v2<<<8192, 128, SMEM_BYTES>>>(q, k, v, mask, out);
}

// round 3
// speedup vs baseline: 1.5349x; 1.1002x over previous
#include <cuda_runtime.h>

typedef unsigned long long u64;

__device__ __forceinline__ u64 fma2(u64 a, u64 b, u64 c) {
    u64 d;
    asm("fma.rn.f32x2 %0, %1, %2, %3;" : "=l"(d) : "l"(a), "l"(b), "l"(c));
    return d;
}
__device__ __forceinline__ void unpack2(u64 v, float& lo, float& hi) {
    asm("mov.b64 {%0, %1}, %2;" : "=f"(lo), "=f"(hi) : "l"(v));
}
__device__ __forceinline__ u64 dup2(float f) {
    u64 d;
    asm("mov.b64 %0, {%1, %1};" : "=l"(d) : "f"(f));
    return d;
}

// Per problem (floats): [0,4096) Q then P; [4096,8192) K then O-staging; [8192,12288) V.
// 48KB/problem, 2 problems/CTA = 96KB -> 2 CTAs/SM (8 warps).
#define PER_PROB 12288
#define SMEM_BYTES (2 * PER_PROB * 4)

__global__ void __launch_bounds__(128, 2)
attn64_v3(const float* __restrict__ qg_, const float* __restrict__ kg_,
          const float* __restrict__ vg_, const int* __restrict__ mg_,
          float* __restrict__ og_)
{
    extern __shared__ float sm[];
    const int tid  = threadIdx.x;
    const int prob = tid >> 6;               // which of the CTA's 2 problems
    const int t    = tid & 63;               // thread-in-problem
    const int ty2  = t >> 3;                 // 0..7 -> rows 8*ty2..8*ty2+7
    const int tx2  = t & 7;                  // 0..7 -> cols {4tx2..+3} u {32+4tx2..+3}

    float* q_s = sm + prob * PER_PROB;       // Q, later P
    float* k_s = q_s + 4096;                 // K, later O staging
    float* v_s = q_s + 8192;                 // V

    const int pg = (blockIdx.x << 1) + prob; // global problem 0..8191
    const float* qg = qg_ + (size_t)pg * 4096;
    const float* kg = kg_ + (size_t)pg * 4096;
    const float* vg = vg_ + (size_t)pg * 4096;
    const int*   mg = mg_ + (size_t)(pg >> 9) * 4096;
    float*       og = og_ + (size_t)pg * 4096;

    // ---- Staging: coalesced 16B gmem loads -> smem (K granule-swizzled) ----
    #pragma unroll
    for (int it = 0; it < 16; it++) {
        int e = (t + (it << 6)) << 2;        // element index, step 4
        int r = e >> 6;
        int h = (e & 63) >> 2;               // 16B granule 0..15
        float4 fq = *reinterpret_cast<const float4*>(qg + e);
        float4 fk = *reinterpret_cast<const float4*>(kg + e);
        float4 fv = *reinterpret_cast<const float4*>(vg + e);
        *reinterpret_cast<float4*>(&q_s[e]) = fq;
        *reinterpret_cast<float4*>(&k_s[(r << 6) + ((h ^ ((r >> 2) & 7)) << 2)]) = fk;
        *reinterpret_cast<float4*>(&v_s[e]) = fv;
    }
    __syncthreads();

    // ---- S = Q K^T : 8x8 register tile, packed over d ----
    u64 acc[8][8];
    #pragma unroll
    for (int i = 0; i < 8; i++)
        #pragma unroll
        for (int j = 0; j < 8; j++) acc[i][j] = 0ull;

    const float* q0 = q_s + ((ty2 << 3) << 6);            // row 8*ty2
    const float* kA = k_s + ((tx2 << 2) << 6);            // rows 4tx2..
    const float* kB = k_s + (((tx2 << 2) + 32) << 6);     // rows 32+4tx2..

    #pragma unroll 4
    for (int g = 0; g < 16; g++) {
        const int koff = (g ^ tx2) << 2;     // uniform for all 8 of this thread's k-rows
        ulonglong2 kv[8];
        #pragma unroll
        for (int j = 0; j < 4; j++) {
            kv[j]     = *reinterpret_cast<const ulonglong2*>(kA + (j << 6) + koff);
            kv[4 + j] = *reinterpret_cast<const ulonglong2*>(kB + (j << 6) + koff);
        }
        #pragma unroll
        for (int i = 0; i < 8; i++) {
            ulonglong2 qv = *reinterpret_cast<const ulonglong2*>(q0 + (i << 6) + (g << 2));
            #pragma unroll
            for (int j = 0; j < 8; j++) {
                acc[i][j] = fma2(qv.x, kv[j].x, acc[i][j]);
                acc[i][j] = fma2(qv.y, kv[j].y, acc[i][j]);
            }
        }
    }
    __syncthreads();   // all warps done reading Q -> safe to overwrite with P

    // ---- Mask fetch (L2-resident, MLP=16) ----
    int4 ma[8], mb[8];
    {
        const int* mrow = mg + (tx2 << 2);
        #pragma unroll
        for (int i = 0; i < 8; i++) {
            int rb = ((ty2 << 3) + i) << 6;
            ma[i] = *reinterpret_cast<const int4*>(mrow + rb);
            mb[i] = *reinterpret_cast<const int4*>(mrow + rb + 32);
        }
    }

    // ---- Softmax in registers; P stored natural (no dup) ----
    float* p0 = q_s + ((ty2 << 3) << 6);
    #pragma unroll
    for (int i = 0; i < 8; i++) {
        int mm[8] = {ma[i].x, ma[i].y, ma[i].z, ma[i].w,
                     mb[i].x, mb[i].y, mb[i].z, mb[i].w};
        float sv[8];
        #pragma unroll
        for (int j = 0; j < 8; j++) {
            float lo, hi;
            unpack2(acc[i][j], lo, hi);
            float tt = (lo + hi) * 0.125f;          // / TEMPERATURE
            sv[j] = (mm[j] == 0) ? -32768.0f : tt;  // MASK_FILL
        }
        float mx = sv[0];
        #pragma unroll
        for (int j = 1; j < 8; j++) mx = fmaxf(mx, sv[j]);
        mx = fmaxf(mx, __shfl_xor_sync(0xffffffffu, mx, 1));
        mx = fmaxf(mx, __shfl_xor_sync(0xffffffffu, mx, 2));
        mx = fmaxf(mx, __shfl_xor_sync(0xffffffffu, mx, 4));
        float pv[8], sum = 0.0f;
        #pragma unroll
        for (int j = 0; j < 8; j++) { pv[j] = __expf(sv[j] - mx); sum += pv[j]; }
        sum += __shfl_xor_sync(0xffffffffu, sum, 1);
        sum += __shfl_xor_sync(0xffffffffu, sum, 2);
        sum += __shfl_xor_sync(0xffffffffu, sum, 4);
        float inv = 1.0f / sum;
        float* pr = p0 + (i << 6);
        *reinterpret_cast<float4*>(pr + (tx2 << 2)) =
            make_float4(pv[0] * inv, pv[1] * inv, pv[2] * inv, pv[3] * inv);
        *reinterpret_cast<float4*>(pr + ((tx2 + 8) << 2)) =
            make_float4(pv[4] * inv, pv[5] * inv, pv[6] * inv, pv[7] * inv);
    }
    __syncthreads();

    // ---- O = P V : 8 rows x 8 cols (2 granules), packed over d ----
    u64 oA[8][2], oB[8][2];
    #pragma unroll
    for (int i = 0; i < 8; i++) {
        oA[i][0] = oA[i][1] = 0ull;
        oB[i][0] = oB[i][1] = 0ull;
    }
    const float* vA = v_s + (tx2 << 2);
    const float* vB = v_s + ((tx2 + 8) << 2);

    #pragma unroll 2
    for (int k4 = 0; k4 < 16; k4++) {
        float4 pr[8];
        #pragma unroll
        for (int i = 0; i < 8; i++)
            pr[i] = *reinterpret_cast<const float4*>(p0 + (i << 6) + (k4 << 2));
        #pragma unroll
        for (int kk = 0; kk < 4; kk++) {
            int krow = (((k4 << 2) + kk) << 6);
            ulonglong2 va = *reinterpret_cast<const ulonglong2*>(vA + krow);
            ulonglong2 vb = *reinterpret_cast<const ulonglong2*>(vB + krow);
            #pragma unroll
            for (int i = 0; i < 8; i++) {
                const float* prf = reinterpret_cast<const float*>(&pr[i]);
                u64 pp = dup2(prf[kk]);
                oA[i][0] = fma2(pp, va.x, oA[i][0]);
                oA[i][1] = fma2(pp, va.y, oA[i][1]);
                oB[i][0] = fma2(pp, vb.x, oB[i][0]);
                oB[i][1] = fma2(pp, vb.y, oB[i][1]);
            }
        }
    }

    // ---- Stage O (natural layout) into k_s. Safe: all warps passed the
    // post-P barrier, so no warp is still reading K. ----
    #pragma unroll
    for (int i = 0; i < 8; i++) {
        float* orow = k_s + (((ty2 << 3) + i) << 6);
        ulonglong2 tA; tA.x = oA[i][0]; tA.y = oA[i][1];
        ulonglong2 tB; tB.x = oB[i][0]; tB.y = oB[i][1];
        *reinterpret_cast<ulonglong2*>(orow + (tx2 << 2))       = tA;
        *reinterpret_cast<ulonglong2*>(orow + ((tx2 + 8) << 2)) = tB;
    }
    __syncthreads();

    // ---- Fully coalesced 16B stores ----
    #pragma unroll
    for (int it = 0; it < 16; it++) {
        int e = (t + (it << 6)) << 2;
        *reinterpret_cast<float4*>(og + e) =
            *reinterpret_cast<const float4*>(k_s + e);
    }
}

extern "C" void kernel_launch(void* const* d_in, const int* in_sizes, int n_in,
                              void* d_out, int out_size) {
    const float* q    = (const float*)d_in[0];
    const float* k    = (const float*)d_in[1];
    const float* v    = (const float*)d_in[2];
    const int*   mask = (const int*)  d_in[3];
    float*       out  = (float*)d_out;

    cudaFuncSetAttribute(attn64_v3,
                         cudaFuncAttributeMaxDynamicSharedMemorySize, SMEM_BYTES);
    attn64_v3<<<4096, 128, SMEM_BYTES>>>(q, k, v, mask, out);
}

// round 9
// speedup vs baseline: 3.1163x; 2.0303x over previous
#include <cuda_runtime.h>
#include <cstdint>

typedef uint32_t u32;

// smem regions (bytes): bf16 [64 x 64] each, row = 128B, XOR-swizzled granules
#define SM_QH 0
#define SM_QL 8192
#define SM_KH 16384
#define SM_KL 24576
#define SM_VH 32768
#define SM_VL 40960
#define SMEM_BYTES 49152
// O staging (f32, stride 68 floats) overlays QH/QL/KH after QK is done

__device__ __forceinline__ u32 smem_u32(const void* p) {
    u32 a;
    asm("{ .reg .u64 t; cvta.to.shared.u64 t, %1; cvt.u32.u64 %0, t; }" : "=r"(a) : "l"(p));
    return a;
}
__device__ __forceinline__ u32 pack_h(float f0, float f1) {   // lo=f0, hi=f1
    u32 r;
    asm("cvt.rn.bf16x2.f32 %0, %1, %2;" : "=r"(r) : "f"(f1), "f"(f0));
    return r;
}
__device__ __forceinline__ u32 pack_l(u32 h, float f0, float f1) {
    float r0 = f0 - __uint_as_float(h << 16);
    float r1 = f1 - __uint_as_float(h & 0xffff0000u);
    return pack_h(r0, r1);
}
__device__ __forceinline__ void ldsm4(u32* r, u32 addr) {
    asm volatile("ldmatrix.sync.aligned.m8n8.x4.shared.b16 {%0,%1,%2,%3}, [%4];"
        : "=r"(r[0]), "=r"(r[1]), "=r"(r[2]), "=r"(r[3]) : "r"(addr));
}
__device__ __forceinline__ void ldsm4t(u32* r, u32 addr) {
    asm volatile("ldmatrix.sync.aligned.m8n8.x4.trans.shared.b16 {%0,%1,%2,%3}, [%4];"
        : "=r"(r[0]), "=r"(r[1]), "=r"(r[2]), "=r"(r[3]) : "r"(addr));
}
__device__ __forceinline__ void mma16816(float* c, const u32* a, const u32* b) {
    asm volatile(
        "mma.sync.aligned.m16n8k16.row.col.f32.bf16.bf16.f32 "
        "{%0,%1,%2,%3}, {%4,%5,%6,%7}, {%8,%9}, {%0,%1,%2,%3};"
        : "+f"(c[0]), "+f"(c[1]), "+f"(c[2]), "+f"(c[3])
        : "r"(a[0]), "r"(a[1]), "r"(a[2]), "r"(a[3]), "r"(b[0]), "r"(b[1]));
}

__global__ void __launch_bounds__(128, 4)
attn64_wmma(const float* __restrict__ qg_, const float* __restrict__ kg_,
            const float* __restrict__ vg_, const int* __restrict__ mg_,
            float* __restrict__ og_)
{
    extern __shared__ char smem[];
    const u32 sbase = smem_u32(smem);
    const int tid  = threadIdx.x;
    const int lane = tid & 31;
    const int w    = tid >> 5;

    const int pg = blockIdx.x;                   // one 64x64x64 problem per CTA
    const float* qg = qg_ + (size_t)pg * 4096;
    const float* kg = kg_ + (size_t)pg * 4096;
    const float* vg = vg_ + (size_t)pg * 4096;
    const int*   mg = mg_ + (size_t)(pg >> 9) * 4096;
    float*       og = og_ + (size_t)pg * 4096;

    // ---- Stage Q,K,V: fp32 -> (hi,lo) bf16, swizzled (granule ^ (row&7)) ----
    // 512 granules per tensor, 128 threads -> 4 iterations (NOT 8: that was the
    // round-8 OOB bug — smem region overrun + gmem read past array end).
    #pragma unroll
    for (int it = 0; it < 4; it++) {
        int idx = tid + (it << 7);               // 0..511, one 16B granule each
        int e = idx << 3;                        // 8 source floats
        int r = idx >> 3;                        // row 0..63
        int h = idx & 7;                         // granule 0..7
        int off = (r << 7) + ((h ^ (r & 7)) << 4);
        float4 f0, f1;
        uint4 hq, lq;

        f0 = *reinterpret_cast<const float4*>(qg + e);
        f1 = *reinterpret_cast<const float4*>(qg + e + 4);
        hq.x = pack_h(f0.x, f0.y); hq.y = pack_h(f0.z, f0.w);
        hq.z = pack_h(f1.x, f1.y); hq.w = pack_h(f1.z, f1.w);
        lq.x = pack_l(hq.x, f0.x, f0.y); lq.y = pack_l(hq.y, f0.z, f0.w);
        lq.z = pack_l(hq.z, f1.x, f1.y); lq.w = pack_l(hq.w, f1.z, f1.w);
        *reinterpret_cast<uint4*>(smem + SM_QH + off) = hq;
        *reinterpret_cast<uint4*>(smem + SM_QL + off) = lq;

        f0 = *reinterpret_cast<const float4*>(kg + e);
        f1 = *reinterpret_cast<const float4*>(kg + e + 4);
        hq.x = pack_h(f0.x, f0.y); hq.y = pack_h(f0.z, f0.w);
        hq.z = pack_h(f1.x, f1.y); hq.w = pack_h(f1.z, f1.w);
        lq.x = pack_l(hq.x, f0.x, f0.y); lq.y = pack_l(hq.y, f0.z, f0.w);
        lq.z = pack_l(hq.z, f1.x, f1.y); lq.w = pack_l(hq.w, f1.z, f1.w);
        *reinterpret_cast<uint4*>(smem + SM_KH + off) = hq;
        *reinterpret_cast<uint4*>(smem + SM_KL + off) = lq;

        f0 = *reinterpret_cast<const float4*>(vg + e);
        f1 = *reinterpret_cast<const float4*>(vg + e + 4);
        hq.x = pack_h(f0.x, f0.y); hq.y = pack_h(f0.z, f0.w);
        hq.z = pack_h(f1.x, f1.y); hq.w = pack_h(f1.z, f1.w);
        lq.x = pack_l(hq.x, f0.x, f0.y); lq.y = pack_l(hq.y, f0.z, f0.w);
        lq.z = pack_l(hq.z, f1.x, f1.y); lq.w = pack_l(hq.w, f1.z, f1.w);
        *reinterpret_cast<uint4*>(smem + SM_VH + off) = hq;
        *reinterpret_cast<uint4*>(smem + SM_VL + off) = lq;
    }
    __syncthreads();

    // ---- ldmatrix address templates (all swizzle terms use lane&7 = row&7) ----
    const int sw    = lane & 7;
    const int a_row = (w << 4) + (lane & 7) + (((lane >> 3) & 1) << 3);
    const int a_ga  = lane >> 4;                          // A order: (r,g)(r8,g)(r,g1)(r8,g1)
    const u32 a_base = sbase + (u32)(a_row << 7);
    const int tau = lane >> 3;
    const int kb_radd = ((tau >> 1) << 3) + (lane & 7);   // K order: (r,g)(r,g1)(r8,g)(r8,g1)
    const int kb_ga   = tau & 1;
    const int vb_radd = ((tau & 1) << 3) + (lane & 7);    // V order: (k,g)(k8,g)(k,g1)(k8,g1)
    const int vb_ga   = tau >> 1;

    // ---- S = Q K^T : 3-pass split, 8 N-frags x fp32 accum ----
    float accS[8][4];
    #pragma unroll
    for (int n = 0; n < 8; n++)
        #pragma unroll
        for (int i = 0; i < 4; i++) accS[n][i] = 0.0f;

    #pragma unroll
    for (int kc = 0; kc < 4; kc++) {
        int ag = (kc << 1) + a_ga;
        u32 qh[4], ql[4];
        ldsm4(qh, a_base + SM_QH + ((ag ^ sw) << 4));
        ldsm4(ql, a_base + SM_QL + ((ag ^ sw) << 4));
        int kg_ = (kc << 1) + kb_ga;
        u32 kh[16], kl[16];
        #pragma unroll
        for (int np = 0; np < 4; np++) {
            u32 roff = (u32)(((np << 4) + kb_radd) << 7) + (u32)((kg_ ^ sw) << 4);
            ldsm4(&kh[np << 2], sbase + SM_KH + roff);
            ldsm4(&kl[np << 2], sbase + SM_KL + roff);
        }
        #pragma unroll
        for (int n = 0; n < 8; n++) {
            mma16816(accS[n], qh, &kh[n << 1]);
            mma16816(accS[n], qh, &kl[n << 1]);
            mma16816(accS[n], ql, &kh[n << 1]);
        }
    }
    __syncthreads();   // Q,K smem dead after this -> staging overlay is safe

    // ---- Mask fetch (L2-resident) ----
    const int r0 = (w << 4) + (lane >> 2);
    const int r1 = r0 + 8;
    const int cb = (lane & 3) << 1;
    int2 m0[8], m1[8];
    #pragma unroll
    for (int n = 0; n < 8; n++) {
        m0[n] = *reinterpret_cast<const int2*>(mg + (r0 << 6) + (n << 3) + cb);
        m1[n] = *reinterpret_cast<const int2*>(mg + (r1 << 6) + (n << 3) + cb);
    }

    // ---- Softmax fully in registers (quad shuffles over the 4 col-lanes) ----
    float p0[16], p1[16];
    #pragma unroll
    for (int n = 0; n < 8; n++) {
        p0[2*n]   = (m0[n].x == 0) ? -32768.0f : accS[n][0] * 0.125f;
        p0[2*n+1] = (m0[n].y == 0) ? -32768.0f : accS[n][1] * 0.125f;
        p1[2*n]   = (m1[n].x == 0) ? -32768.0f : accS[n][2] * 0.125f;
        p1[2*n+1] = (m1[n].y == 0) ? -32768.0f : accS[n][3] * 0.125f;
    }
    float mx0 = p0[0], mx1 = p1[0];
    #pragma unroll
    for (int j = 1; j < 16; j++) { mx0 = fmaxf(mx0, p0[j]); mx1 = fmaxf(mx1, p1[j]); }
    mx0 = fmaxf(mx0, __shfl_xor_sync(0xffffffffu, mx0, 1));
    mx0 = fmaxf(mx0, __shfl_xor_sync(0xffffffffu, mx0, 2));
    mx1 = fmaxf(mx1, __shfl_xor_sync(0xffffffffu, mx1, 1));
    mx1 = fmaxf(mx1, __shfl_xor_sync(0xffffffffu, mx1, 2));
    float s0 = 0.0f, s1 = 0.0f;
    #pragma unroll
    for (int j = 0; j < 16; j++) {
        p0[j] = __expf(p0[j] - mx0); s0 += p0[j];
        p1[j] = __expf(p1[j] - mx1); s1 += p1[j];
    }
    s0 += __shfl_xor_sync(0xffffffffu, s0, 1);
    s0 += __shfl_xor_sync(0xffffffffu, s0, 2);
    s1 += __shfl_xor_sync(0xffffffffu, s1, 1);
    s1 += __shfl_xor_sync(0xffffffffu, s1, 2);
    const float i0 = 1.0f / s0, i1 = 1.0f / s1;
    #pragma unroll
    for (int j = 0; j < 16; j++) { p0[j] *= i0; p1[j] *= i1; }

    // ---- Pack P into A-fragments (hi,lo) directly in registers ----
    u32 ph[4][4], pl[4][4];
    #pragma unroll
    for (int kc = 0; kc < 4; kc++) {
        ph[kc][0] = pack_h(p0[4*kc],   p0[4*kc+1]);
        ph[kc][1] = pack_h(p1[4*kc],   p1[4*kc+1]);
        ph[kc][2] = pack_h(p0[4*kc+2], p0[4*kc+3]);
        ph[kc][3] = pack_h(p1[4*kc+2], p1[4*kc+3]);
        pl[kc][0] = pack_l(ph[kc][0], p0[4*kc],   p0[4*kc+1]);
        pl[kc][1] = pack_l(ph[kc][1], p1[4*kc],   p1[4*kc+1]);
        pl[kc][2] = pack_l(ph[kc][2], p0[4*kc+2], p0[4*kc+3]);
        pl[kc][3] = pack_l(ph[kc][3], p1[4*kc+2], p1[4*kc+3]);
    }

    // ---- O = P V : 3-pass split, V B-frags via ldmatrix.trans ----
    float oacc[8][4];
    #pragma unroll
    for (int n = 0; n < 8; n++)
        #pragma unroll
        for (int i = 0; i < 4; i++) oacc[n][i] = 0.0f;

    #pragma unroll
    for (int kc = 0; kc < 4; kc++) {
        u32 vh[16], vl[16];
        #pragma unroll
        for (int np = 0; np < 4; np++) {
            int vg_ = (np << 1) + vb_ga;
            u32 roff = (u32)(((kc << 4) + vb_radd) << 7) + (u32)((vg_ ^ sw) << 4);
            ldsm4t(&vh[np << 2], sbase + SM_VH + roff);
            ldsm4t(&vl[np << 2], sbase + SM_VL + roff);
        }
        #pragma unroll
        for (int n = 0; n < 8; n++) {
            mma16816(oacc[n], ph[kc], &vh[n << 1]);
            mma16816(oacc[n], ph[kc], &vl[n << 1]);
            mma16816(oacc[n], pl[kc], &vh[n << 1]);
        }
    }

    // ---- Stage O (f32, stride 68) into dead Q/K smem; coalesced stores ----
    float* stag = reinterpret_cast<float*>(smem);
    #pragma unroll
    for (int n = 0; n < 8; n++) {
        *reinterpret_cast<float2*>(stag + r0 * 68 + (n << 3) + cb) =
            make_float2(oacc[n][0], oacc[n][1]);
        *reinterpret_cast<float2*>(stag + r1 * 68 + (n << 3) + cb) =
            make_float2(oacc[n][2], oacc[n][3]);
    }
    __syncthreads();
    #pragma unroll
    for (int it = 0; it < 8; it++) {
        int e = (tid + (it << 7)) << 2;
        int r = e >> 6, c = e & 63;
        *reinterpret_cast<float4*>(og + e) =
            *reinterpret_cast<const float4*>(stag + r * 68 + c);
    }
}

extern "C" void kernel_launch(void* const* d_in, const int* in_sizes, int n_in,
                              void* d_out, int out_size) {
    const float* q    = (const float*)d_in[0];
    const float* k    = (const float*)d_in[1];
    const float* v    = (const float*)d_in[2];
    const int*   mask = (const int*)  d_in[3];
    float*       out  = (float*)d_out;

    cudaFuncSetAttribute(attn64_wmma,
                         cudaFuncAttributeMaxDynamicSharedMemorySize, SMEM_BYTES);
    attn64_wmma<<<8192, 128, SMEM_BYTES>>>(q, k, v, mask, out);
}